// round 1
// baseline (speedup 1.0000x reference)
#include <cuda_runtime.h>

// Problem constants
#define B_    16
#define CIN   256
#define COUT  128
#define HW    64     // input H = W
#define OHW   128    // output H = W
#define KDIM  1024   // CIN * 4 taps per phase

// Scratch: synthesized per-sample weights in GEMM layout:
// g_wsyn[b][phase p=py*2+px][k = ci*4 + ty*2 + tx][co]
// 16 * 4 * 1024 * 128 floats = 33.5 MB
__device__ __align__(16) float g_wsyn[B_ * 4 * KDIM * COUT];

// ---------------------------------------------------------------------------
// Kernel 1: weight synthesis.
// One thread per (ci, co, ky, kx). Reads weight/t_j/m_j once, writes 16 batches.
// Tap mapping (derived from flip+swapaxes in the reference):
//   py = 1 - (ky & 1); dy = (py + 1 - ky)/2;  ty = dy + 1 - py   (ty in {0,1})
// so that in the GEMM, k = ci*4 + ty*2 + tx gathers x[ci, y + (ty-1+py), x + (tx-1+px)].
// ---------------------------------------------------------------------------
__global__ void synth_kernel(const float* __restrict__ feature,
                             const float* __restrict__ weight,
                             const float* __restrict__ t0,
                             const float* __restrict__ t1,
                             const float* __restrict__ t2,
                             const float* __restrict__ t3,
                             const float* __restrict__ m0,
                             const float* __restrict__ m1,
                             const float* __restrict__ m2,
                             const float* __restrict__ m3) {
    __shared__ float sf[B_ * 4];
    if (threadIdx.x < B_ * 4) sf[threadIdx.x] = feature[threadIdx.x];
    __syncthreads();

    int idx = blockIdx.x * blockDim.x + threadIdx.x;  // over CIN*COUT*16
    if (idx >= CIN * COUT * 16) return;

    int kx = idx & 3;
    int ky = (idx >> 2) & 3;
    int co = (idx >> 4) & (COUT - 1);
    int ci = idx >> 11;

    float w = weight[idx];
    int mi = ci * COUT + co;
    float a0 = t0[idx] * m0[mi];
    float a1 = t1[idx] * m1[mi];
    float a2 = t2[idx] * m2[mi];
    float a3 = t3[idx] * m3[mi];

    int py = 1 - (ky & 1);
    int px = 1 - (kx & 1);
    int dy = (py + 1 - ky) / 2;   // exact for even numerators (2,0,-2)
    int dx = (px + 1 - kx) / 2;
    int ty = dy + 1 - py;
    int tx = dx + 1 - px;
    int p  = py * 2 + px;
    int k  = ci * 4 + ty * 2 + tx;

    size_t base     = ((size_t)p * KDIM + k) * COUT + co;
    size_t stride_b = (size_t)4 * KDIM * COUT;

#pragma unroll
    for (int b = 0; b < B_; b++) {
        const float* f = sf + b * 4;
        g_wsyn[b * stride_b + base] = w + a0 * f[0] + a1 * f[1] + a2 * f[2] + a3 * f[3];
    }
}

// ---------------------------------------------------------------------------
// Kernel 2: phase GEMM (implicit im2col), fp32 FFMA.
// Per CTA: one (batch, phase, 128-wide spatial tile).
//   M = COUT = 128 (full), N = 128 spatial positions (2 y-rows x 64 x),
//   K = 1024, stepped by 8 through shared memory.
// 256 threads, each computes an 8(co) x 8(n) register tile.
// Epilogue: + bias, PReLU, scatter to strided output phase positions.
// ---------------------------------------------------------------------------
__global__ void __launch_bounds__(256)
deconv_gemm_kernel(const float* __restrict__ x,
                   const float* __restrict__ bias,
                   const float* __restrict__ prelu_a,
                   float* __restrict__ out) {
    const int b  = blockIdx.z;
    const int p  = blockIdx.y;
    const int py = p >> 1, px = p & 1;
    const int n0 = blockIdx.x * 128;        // spatial tile start (n = y*64 + x)
    const int y0 = n0 >> 6;

    __shared__ float Ws[8][COUT];           // [kk][co]
    __shared__ float Xs[8][128];            // [kk][n]

    float acc[8][8];
#pragma unroll
    for (int i = 0; i < 8; i++)
#pragma unroll
        for (int j = 0; j < 8; j++) acc[i][j] = 0.f;

    const int tid    = threadIdx.x;
    const int cofrag = (tid >> 4) << 3;     // 0..120 step 8
    const int nfrag  = (tid & 15) << 3;     // 0..120 step 8

    const float* wb = g_wsyn + ((size_t)b * 4 + p) * KDIM * COUT;
    const float* xb = x + (size_t)b * CIN * HW * HW;

    const int ldrow = tid >> 5;             // 0..7 : which k-row this thread loads
    const int jbase = (tid & 31) * 4;       // 0..124: n offset for X load / co offset for W load

    for (int k0 = 0; k0 < KDIM; k0 += 8) {
        // --- stage W slice: 8 x 128, one float4 per thread, coalesced ---
        {
            const float4 wv = *(const float4*)(wb + (size_t)(k0 + ldrow) * COUT + jbase);
            *(float4*)(&Ws[ldrow][jbase]) = wv;
        }
        // --- stage X slice: 8 x 128 implicit-im2col gather ---
        {
            int k  = k0 + ldrow;
            int ci = k >> 2;
            int ty = (k >> 1) & 1;
            int tx = k & 1;
            int dy = ty - 1 + py;
            int dx = tx - 1 + px;
            const float* xc = xb + (size_t)ci * HW * HW;
#pragma unroll
            for (int u = 0; u < 4; u++) {
                int j  = jbase + u;
                int y  = y0 + (j >> 6);
                int xx = j & 63;
                int iy = y + dy;
                int ix = xx + dx;
                float v = 0.f;
                if ((unsigned)iy < (unsigned)HW && (unsigned)ix < (unsigned)HW)
                    v = xc[iy * HW + ix];
                Xs[ldrow][j] = v;
            }
        }
        __syncthreads();

#pragma unroll
        for (int kk = 0; kk < 8; kk++) {
            float wr[8], xr[8];
#pragma unroll
            for (int i = 0; i < 8; i++) wr[i] = Ws[kk][cofrag + i];
#pragma unroll
            for (int j = 0; j < 8; j++) xr[j] = Xs[kk][nfrag + j];
#pragma unroll
            for (int i = 0; i < 8; i++)
#pragma unroll
                for (int j = 0; j < 8; j++)
                    acc[i][j] += wr[i] * xr[j];
        }
        __syncthreads();
    }

    // --- epilogue: bias + PReLU + scatter to phase positions ---
    const float alpha = prelu_a[0];
#pragma unroll
    for (int i = 0; i < 8; i++) {
        const int co = cofrag + i;
        const float bv = bias[co];
        float* orow = out + ((size_t)b * COUT + co) * OHW * OHW;
#pragma unroll
        for (int j = 0; j < 8; j++) {
            int n  = n0 + nfrag + j;
            int y  = n >> 6;
            int xx = n & 63;
            int oy = 2 * y + py;
            int ox = 2 * xx + px;
            float v = acc[i][j] + bv;
            v = (v >= 0.f) ? v : alpha * v;
            orow[oy * OHW + ox] = v;
        }
    }
}

// ---------------------------------------------------------------------------
// Launch
// Inputs (metadata order):
//  0 x (16,256,64,64) f32      1 feature (16,4) f32    2 weight (256,128,4,4)
//  3 t_bayer  4 t_quad  5 t_nano  6 t_qxq  (1,256,128,4,4)
//  7 m_bayer  8 m_quad  9 m_nano 10 m_qxq  (1,256,128,1,1)
// 11 bias (128,)   12 prelu_a (1,)
// Output: (16,128,128,128) f32
// ---------------------------------------------------------------------------
extern "C" void kernel_launch(void* const* d_in, const int* in_sizes, int n_in,
                              void* d_out, int out_size) {
    const float* x       = (const float*)d_in[0];
    const float* feature = (const float*)d_in[1];
    const float* weight  = (const float*)d_in[2];
    const float* t0      = (const float*)d_in[3];
    const float* t1      = (const float*)d_in[4];
    const float* t2      = (const float*)d_in[5];
    const float* t3      = (const float*)d_in[6];
    const float* m0      = (const float*)d_in[7];
    const float* m1      = (const float*)d_in[8];
    const float* m2      = (const float*)d_in[9];
    const float* m3      = (const float*)d_in[10];
    const float* bias    = (const float*)d_in[11];
    const float* prelu_a = (const float*)d_in[12];
    float* out = (float*)d_out;

    {
        int total = CIN * COUT * 16;
        int threads = 256;
        int blocks = (total + threads - 1) / threads;
        synth_kernel<<<blocks, threads>>>(feature, weight, t0, t1, t2, t3,
                                          m0, m1, m2, m3);
    }
    {
        dim3 grid(32, 4, B_);   // 32 spatial tiles x 4 phases x 16 batches
        deconv_gemm_kernel<<<grid, 256>>>(x, bias, prelu_a, out);
    }
}

// round 2
// speedup vs baseline: 2.7948x; 2.7948x over previous
#include <cuda_runtime.h>
#include <cuda_fp16.h>

// Problem constants
#define B_    16
#define CIN   256
#define COUT  128
#define HW    64     // input H = W
#define OHW   128    // output H = W
#define KDIM  1024   // CIN * 4 taps per phase
#define KS    32     // K-step per smem stage
#define WSTR  40     // padded smem row stride (halfs) -> conflict-free frag loads

// Scratch:
//  g_wsyn_h[b][p][co][k]  (half)  16*4*128*1024 = 8.4M halfs = 16 MB
//  g_xh     same layout as x (half) 16*256*64*64 = 16.8M halfs = 33.5 MB
__device__ __align__(16) __half g_wsyn_h[B_ * 4 * COUT * KDIM];
__device__ __align__(16) __half g_xh[B_ * CIN * HW * HW];

// ---------------------------------------------------------------------------
// Kernel 0: convert x (fp32) -> half, linear layout.
// ---------------------------------------------------------------------------
__global__ void convert_x_kernel(const float* __restrict__ x) {
    int i = blockIdx.x * blockDim.x + threadIdx.x;   // over N/4 float4s
    const int n4 = (B_ * CIN * HW * HW) / 4;
    if (i >= n4) return;
    float4 v = ((const float4*)x)[i];
    half2 h0 = __floats2half2_rn(v.x, v.y);
    half2 h1 = __floats2half2_rn(v.z, v.w);
    ((half2*)g_xh)[2 * i]     = h0;
    ((half2*)g_xh)[2 * i + 1] = h1;
}

// ---------------------------------------------------------------------------
// Kernel 1: weight synthesis -> half, GEMM layout [b][p][co][k].
// k = ci*4 + ty*2 + tx, where (ty,tx) are the im2col taps for phase (py,px):
//   py = 1-(ky&1); dy = (py+1-ky)/2; ty = dy+1-py   (same math as verified R1)
// ---------------------------------------------------------------------------
__global__ void synth_kernel(const float* __restrict__ feature,
                             const float* __restrict__ weight,
                             const float* __restrict__ t0,
                             const float* __restrict__ t1,
                             const float* __restrict__ t2,
                             const float* __restrict__ t3,
                             const float* __restrict__ m0,
                             const float* __restrict__ m1,
                             const float* __restrict__ m2,
                             const float* __restrict__ m3) {
    __shared__ float sf[B_ * 4];
    if (threadIdx.x < B_ * 4) sf[threadIdx.x] = feature[threadIdx.x];
    __syncthreads();

    int idx = blockIdx.x * blockDim.x + threadIdx.x;  // over CIN*COUT*16
    if (idx >= CIN * COUT * 16) return;

    int kx = idx & 3;
    int ky = (idx >> 2) & 3;
    int co = (idx >> 4) & (COUT - 1);
    int ci = idx >> 11;

    float w = weight[idx];
    int mi = ci * COUT + co;
    float a0 = t0[idx] * m0[mi];
    float a1 = t1[idx] * m1[mi];
    float a2 = t2[idx] * m2[mi];
    float a3 = t3[idx] * m3[mi];

    int py = 1 - (ky & 1);
    int px = 1 - (kx & 1);
    int dy = (py + 1 - ky) / 2;
    int dx = (px + 1 - kx) / 2;
    int ty = dy + 1 - py;
    int tx = dx + 1 - px;
    int p  = py * 2 + px;
    int k  = ci * 4 + ty * 2 + tx;

    size_t base     = ((size_t)p * COUT + co) * KDIM + k;
    size_t stride_b = (size_t)4 * COUT * KDIM;

#pragma unroll
    for (int b = 0; b < B_; b++) {
        const float* f = sf + b * 4;
        g_wsyn_h[b * stride_b + base] =
            __float2half(w + a0 * f[0] + a1 * f[1] + a2 * f[2] + a3 * f[3]);
    }
}

// ---------------------------------------------------------------------------
// Kernel 2: phase GEMM on tensor cores (mma.sync m16n8k16 f16->f32).
// Per CTA: (batch, phase, 128-spatial tile). M=COUT=128, N=128, K=1024.
// 8 warps in a 2(m) x 4(n) grid; each warp computes 64x32 via 4x4 m16n8 tiles.
// Smem tiles are K-contiguous with row stride 40 halfs (conflict-free LDS).
// ---------------------------------------------------------------------------
__device__ __forceinline__ void mma16816(float c[4], unsigned a0, unsigned a1,
                                         unsigned a2, unsigned a3,
                                         unsigned b0, unsigned b1) {
    asm volatile(
        "mma.sync.aligned.m16n8k16.row.col.f32.f16.f16.f32 "
        "{%0,%1,%2,%3}, {%4,%5,%6,%7}, {%8,%9}, {%0,%1,%2,%3};\n"
        : "+f"(c[0]), "+f"(c[1]), "+f"(c[2]), "+f"(c[3])
        : "r"(a0), "r"(a1), "r"(a2), "r"(a3), "r"(b0), "r"(b1));
}

__global__ void __launch_bounds__(256)
deconv_mma_kernel(const float* __restrict__ bias,
                  const float* __restrict__ prelu_a,
                  float* __restrict__ out) {
    const int b  = blockIdx.z;
    const int p  = blockIdx.y;
    const int py = p >> 1, px = p & 1;
    const int n0 = blockIdx.x * 128;        // spatial tile start (n = y*64 + x)
    const int y0 = n0 >> 6;

    __shared__ __half Ws[128 * WSTR];       // [co][k]  A tile
    __shared__ __half Xs[128 * WSTR];       // [n][k]   B tile (K-contiguous)

    const int tid    = threadIdx.x;
    const int lane   = tid & 31;
    const int warp   = tid >> 5;
    const int warp_m = warp >> 2;           // 0..1  (64 rows each)
    const int warp_n = warp & 3;            // 0..3  (32 cols each)

    float acc[4][4][4];
#pragma unroll
    for (int i = 0; i < 4; i++)
#pragma unroll
        for (int j = 0; j < 4; j++)
#pragma unroll
            for (int r = 0; r < 4; r++) acc[i][j][r] = 0.f;

    const __half* wb = g_wsyn_h + ((size_t)(b * 4 + p) * COUT) * KDIM;
    const __half* xb = g_xh + (size_t)b * CIN * HW * HW;

    // staging roles: 2 threads per row, 16 halfs (32B) each
    const int srow  = tid >> 1;             // 0..127
    const int shalf = (tid & 1) * 16;       // 0 or 16

    // Precompute x-gather geometry for this thread's row (n = srow)
    const int gy  = y0 + (srow >> 6);       // input y for this n
    const int gx  = srow & 63;

    for (int k0 = 0; k0 < KDIM; k0 += KS) {
        // --- stage A: Ws[co][k], 32B per thread, coalesced ---
        {
            const uint4* src = (const uint4*)(wb + (size_t)srow * KDIM + k0 + shalf);
            uint4 w0 = src[0];
            uint4 w1 = src[1];
            uint4* dst = (uint4*)(Ws + srow * WSTR + shalf);
            dst[0] = w0;
            dst[1] = w1;
        }
        // --- stage B: Xs[n][k] implicit-im2col gather (4 ci x 2x2 taps) ---
        {
            __align__(16) __half xv[16];
            const int kbase = k0 + shalf;          // multiple of 16
            const int ci0   = kbase >> 2;
#pragma unroll
            for (int q = 0; q < 4; q++) {
                const __half* xc = xb + (size_t)(ci0 + q) * (HW * HW);
#pragma unroll
                for (int ty = 0; ty < 2; ty++) {
#pragma unroll
                    for (int tx = 0; tx < 2; tx++) {
                        int iy = gy + ty - 1 + py;
                        int ix = gx + tx - 1 + px;
                        __half v = __float2half(0.f);
                        if ((unsigned)iy < (unsigned)HW && (unsigned)ix < (unsigned)HW)
                            v = xc[iy * HW + ix];
                        xv[q * 4 + ty * 2 + tx] = v;
                    }
                }
            }
            uint4* dst = (uint4*)(Xs + srow * WSTR + shalf);
            dst[0] = ((uint4*)xv)[0];
            dst[1] = ((uint4*)xv)[1];
        }
        __syncthreads();

        // --- compute: 2 k-substeps of 16 ---
#pragma unroll
        for (int kk = 0; kk < 2; kk++) {
            const int kc = kk * 16 + (lane & 3) * 2;   // half offset in row
            unsigned bfrag[4][2];
#pragma unroll
            for (int nj = 0; nj < 4; nj++) {
                int nn = warp_n * 32 + nj * 8 + (lane >> 2);
                bfrag[nj][0] = *(const unsigned*)(Xs + nn * WSTR + kc);
                bfrag[nj][1] = *(const unsigned*)(Xs + nn * WSTR + kc + 8);
            }
#pragma unroll
            for (int mi = 0; mi < 4; mi++) {
                int r0 = warp_m * 64 + mi * 16 + (lane >> 2);
                unsigned a0 = *(const unsigned*)(Ws + r0 * WSTR + kc);
                unsigned a1 = *(const unsigned*)(Ws + (r0 + 8) * WSTR + kc);
                unsigned a2 = *(const unsigned*)(Ws + r0 * WSTR + kc + 8);
                unsigned a3 = *(const unsigned*)(Ws + (r0 + 8) * WSTR + kc + 8);
#pragma unroll
                for (int nj = 0; nj < 4; nj++)
                    mma16816(acc[mi][nj], a0, a1, a2, a3, bfrag[nj][0], bfrag[nj][1]);
            }
        }
        __syncthreads();
    }

    // --- epilogue: bias + PReLU + stride-2 phase scatter ---
    const float alpha = prelu_a[0];
#pragma unroll
    for (int mi = 0; mi < 4; mi++) {
        const int rbase = warp_m * 64 + mi * 16 + (lane >> 2);
#pragma unroll
        for (int half_m = 0; half_m < 2; half_m++) {
            const int co = rbase + half_m * 8;
            const float bv = bias[co];
            float* obase = out + ((size_t)b * COUT + co) * OHW * OHW;
#pragma unroll
            for (int nj = 0; nj < 4; nj++) {
#pragma unroll
                for (int u = 0; u < 2; u++) {
                    int n  = n0 + warp_n * 32 + nj * 8 + (lane & 3) * 2 + u;
                    int y  = n >> 6;
                    int xx = n & 63;
                    int oy = 2 * y + py;
                    int ox = 2 * xx + px;
                    float v = acc[mi][nj][half_m * 2 + u] + bv;
                    v = (v >= 0.f) ? v : alpha * v;
                    obase[oy * OHW + ox] = v;
                }
            }
        }
    }
}

// ---------------------------------------------------------------------------
// Launch
// ---------------------------------------------------------------------------
extern "C" void kernel_launch(void* const* d_in, const int* in_sizes, int n_in,
                              void* d_out, int out_size) {
    const float* x       = (const float*)d_in[0];
    const float* feature = (const float*)d_in[1];
    const float* weight  = (const float*)d_in[2];
    const float* t0      = (const float*)d_in[3];
    const float* t1      = (const float*)d_in[4];
    const float* t2      = (const float*)d_in[5];
    const float* t3      = (const float*)d_in[6];
    const float* m0      = (const float*)d_in[7];
    const float* m1      = (const float*)d_in[8];
    const float* m2      = (const float*)d_in[9];
    const float* m3      = (const float*)d_in[10];
    const float* bias    = (const float*)d_in[11];
    const float* prelu_a = (const float*)d_in[12];
    float* out = (float*)d_out;

    {
        int n4 = (B_ * CIN * HW * HW) / 4;
        convert_x_kernel<<<(n4 + 255) / 256, 256>>>(x);
    }
    {
        int total = CIN * COUT * 16;
        synth_kernel<<<(total + 255) / 256, 256>>>(feature, weight, t0, t1, t2, t3,
                                                   m0, m1, m2, m3);
    }
    {
        dim3 grid(32, 4, B_);   // 32 spatial tiles x 4 phases x 16 batches
        deconv_mma_kernel<<<grid, 256>>>(bias, prelu_a, out);
    }
}

// round 3
// speedup vs baseline: 6.1783x; 2.2106x over previous
#include <cuda_runtime.h>
#include <cuda_fp16.h>

// Problem constants
#define B_    16
#define CIN   256
#define COUT  128
#define HW    64
#define OHW   128
#define KDIM  1024   // CIN * 4 taps per phase
#define KS    64     // K halfs per smem stage
#define STAGE_BYTES 32768  // A 16KB + B 16KB

// Scratch:
//  g_wsyn_h[b][p][co][k]          16 MB
//  g_xs3[dx+1][b][ci][66][64]     3 shifted, y-padded half copies of x, 104 MB
__device__ __align__(16) __half g_wsyn_h[B_ * 4 * COUT * KDIM];
__device__ __align__(16) __half g_xs3[3ull * B_ * CIN * 66 * 64];

// ---------------------------------------------------------------------------
// Kernel 0: build the 3 shifted/padded half copies of x.
// xs3[d][b][ci][row][xx] = x[b][ci][row-1][xx + d - 1], zero outside bounds.
// One thread per (b,ci,row, 8-xx chunk): 1x read of x, 3x 16B writes.
// ---------------------------------------------------------------------------
__global__ void prep_x_kernel(const float* __restrict__ x) {
    int idx = blockIdx.x * blockDim.x + threadIdx.x;
    const int total = B_ * CIN * 66 * 8;
    if (idx >= total) return;
    int j   = idx & 7;
    int row = (idx >> 3) % 66;
    int ci  = (idx >> 3) / 66 % CIN;
    int b   = idx / (8 * 66 * CIN);
    int y   = row - 1;

    const size_t dstr  = (size_t)B_ * CIN * 66 * 64;
    size_t       dbase = ((size_t)b * CIN + ci) * (66 * 64) + row * 64 + j * 8;

    if ((unsigned)y >= (unsigned)HW) {
        uint4 z = make_uint4(0, 0, 0, 0);
        *(uint4*)(g_xs3 + dbase)            = z;
        *(uint4*)(g_xs3 + dstr + dbase)     = z;
        *(uint4*)(g_xs3 + 2 * dstr + dbase) = z;
        return;
    }
    const float* xr = x + (((size_t)b * CIN + ci) * HW + y) * HW;
    float4 fa = *(const float4*)(xr + j * 8);
    float4 fb = *(const float4*)(xr + j * 8 + 4);
    float fm1 = j ? xr[j * 8 - 1] : 0.f;
    float fp8 = (j < 7) ? xr[j * 8 + 8] : 0.f;

    __half h0 = __float2half(fa.x), h1 = __float2half(fa.y);
    __half h2 = __float2half(fa.z), h3 = __float2half(fa.w);
    __half h4 = __float2half(fb.x), h5 = __float2half(fb.y);
    __half h6 = __float2half(fb.z), h7 = __float2half(fb.w);
    __half hm = __float2half(fm1),  hp = __float2half(fp8);

    __align__(16) __half L[8] = {hm, h0, h1, h2, h3, h4, h5, h6};  // dx = -1
    __align__(16) __half C[8] = {h0, h1, h2, h3, h4, h5, h6, h7};  // dx =  0
    __align__(16) __half R[8] = {h1, h2, h3, h4, h5, h6, h7, hp};  // dx = +1

    *(uint4*)(g_xs3 + dbase)            = *(uint4*)L;
    *(uint4*)(g_xs3 + dstr + dbase)     = *(uint4*)C;
    *(uint4*)(g_xs3 + 2 * dstr + dbase) = *(uint4*)R;
}

// ---------------------------------------------------------------------------
// Kernel 1: weight synthesis -> half, GEMM layout [b][p][co][k]
// (verified tap math from R1/R2: k = ci*4 + ty*2 + tx).
// ---------------------------------------------------------------------------
__global__ void synth_kernel(const float* __restrict__ feature,
                             const float* __restrict__ weight,
                             const float* __restrict__ t0,
                             const float* __restrict__ t1,
                             const float* __restrict__ t2,
                             const float* __restrict__ t3,
                             const float* __restrict__ m0,
                             const float* __restrict__ m1,
                             const float* __restrict__ m2,
                             const float* __restrict__ m3) {
    __shared__ float sf[B_ * 4];
    if (threadIdx.x < B_ * 4) sf[threadIdx.x] = feature[threadIdx.x];
    __syncthreads();

    int idx = blockIdx.x * blockDim.x + threadIdx.x;
    if (idx >= CIN * COUT * 16) return;

    int kx = idx & 3;
    int ky = (idx >> 2) & 3;
    int co = (idx >> 4) & (COUT - 1);
    int ci = idx >> 11;

    float w = weight[idx];
    int mi = ci * COUT + co;
    float a0 = t0[idx] * m0[mi];
    float a1 = t1[idx] * m1[mi];
    float a2 = t2[idx] * m2[mi];
    float a3 = t3[idx] * m3[mi];

    int py = 1 - (ky & 1);
    int px = 1 - (kx & 1);
    int dy = (py + 1 - ky) / 2;
    int dx = (px + 1 - kx) / 2;
    int ty = dy + 1 - py;
    int tx = dx + 1 - px;
    int p  = py * 2 + px;
    int k  = ci * 4 + ty * 2 + tx;

    size_t base     = ((size_t)p * COUT + co) * KDIM + k;
    size_t stride_b = (size_t)4 * COUT * KDIM;

#pragma unroll
    for (int b = 0; b < B_; b++) {
        const float* f = sf + b * 4;
        g_wsyn_h[b * stride_b + base] =
            __float2half(w + a0 * f[0] + a1 * f[1] + a2 * f[2] + a3 * f[3]);
    }
}

// ---------------------------------------------------------------------------
// Kernel 2: phase GEMM, mma.sync m16n8k16 + ldmatrix + cp.async pipeline.
// CTA tile: M=128 (co) x N=128 (spatial) x K=1024, K-step 64, 2-stage buffer.
// 8 warps in 2(m) x 4(n); warp tile 64x32.
// ---------------------------------------------------------------------------
__device__ __forceinline__ void mma16816(float c[4], unsigned a0, unsigned a1,
                                         unsigned a2, unsigned a3,
                                         unsigned b0, unsigned b1) {
    asm volatile(
        "mma.sync.aligned.m16n8k16.row.col.f32.f16.f16.f32 "
        "{%0,%1,%2,%3}, {%4,%5,%6,%7}, {%8,%9}, {%0,%1,%2,%3};\n"
        : "+f"(c[0]), "+f"(c[1]), "+f"(c[2]), "+f"(c[3])
        : "r"(a0), "r"(a1), "r"(a2), "r"(a3), "r"(b0), "r"(b1));
}
__device__ __forceinline__ void ldsm4(unsigned r[4], unsigned addr) {
    asm volatile("ldmatrix.sync.aligned.m8n8.x4.shared.b16 {%0,%1,%2,%3}, [%4];"
                 : "=r"(r[0]), "=r"(r[1]), "=r"(r[2]), "=r"(r[3]) : "r"(addr));
}
__device__ __forceinline__ void ldsm4t(unsigned r[4], unsigned addr) {
    asm volatile("ldmatrix.sync.aligned.m8n8.x4.trans.shared.b16 {%0,%1,%2,%3}, [%4];"
                 : "=r"(r[0]), "=r"(r[1]), "=r"(r[2]), "=r"(r[3]) : "r"(addr));
}
__device__ __forceinline__ void cpasync16(unsigned dst, const void* src) {
    asm volatile("cp.async.cg.shared.global [%0], [%1], 16;\n" :: "r"(dst), "l"(src));
}

__global__ void __launch_bounds__(256)
deconv_mma_kernel(const float* __restrict__ bias,
                  const float* __restrict__ prelu_a,
                  float* __restrict__ out) {
    extern __shared__ char smem[];
    const int b  = blockIdx.z;
    const int p  = blockIdx.y;
    const int py = p >> 1, px = p & 1;
    const int n0 = blockIdx.x * 128;
    const int y0 = n0 >> 6;

    const int tid    = threadIdx.x;
    const int lane   = tid & 31;
    const int warp   = tid >> 5;
    const int warp_m = warp >> 2;
    const int warp_n = warp & 3;

    const unsigned smem_base = (unsigned)__cvta_generic_to_shared(smem);
    const __half* wb = g_wsyn_h + (size_t)(b * 4 + p) * COUT * KDIM;

    float acc[4][4][4];
#pragma unroll
    for (int i = 0; i < 4; i++)
#pragma unroll
        for (int j = 0; j < 4; j++)
#pragma unroll
            for (int r = 0; r < 4; r++) acc[i][j][r] = 0.f;

    auto issue = [&](int ks, int bs) {
        const int k0 = ks * KS;
        const unsigned abase = smem_base + bs * STAGE_BYTES;
        const unsigned bbase = abase + 16384;
        // A: [co][64k] rows of 128B, swizzled; 4 x 16B per thread
#pragma unroll
        for (int i = 0; i < 4; i++) {
            int seg = tid + i * 256;
            int co = seg >> 3, k8 = seg & 7;
            const __half* src = wb + (size_t)co * KDIM + k0 + k8 * 8;
            unsigned raw = co * 128 + k8 * 16;
            cpasync16(abase + (raw ^ ((co & 7) << 4)), src);
        }
        // B: [k][128n] rows of 256B, swizzled; contiguous shifted-x segments
#pragma unroll
        for (int i = 0; i < 4; i++) {
            int seg = tid + i * 256;
            int kr = seg >> 4, j = seg & 15;
            int k  = k0 + kr;
            int ci = k >> 2, ty = (k >> 1) & 1, tx = k & 1;
            int d    = tx + px;                 // shifted-copy index (dx+1)
            int rrow = y0 + (j >> 3) + ty + py; // padded row (dy + 1 folded in)
            const __half* src = g_xs3 +
                ((size_t)d * B_ * CIN + (size_t)b * CIN + ci) * (66 * 64) +
                rrow * 64 + (j & 7) * 8;
            unsigned raw = kr * 256 + j * 16;
            cpasync16(bbase + (raw ^ ((kr & 7) << 4)), src);
        }
        asm volatile("cp.async.commit_group;\n" ::: "memory");
    };

    auto compute = [&](int bs) {
        const unsigned abase = smem_base + bs * STAGE_BYTES;
        const unsigned bbase = abase + 16384;
#pragma unroll
        for (int kk = 0; kk < 4; kk++) {
            unsigned afr[4][4];
#pragma unroll
            for (int mi = 0; mi < 4; mi++) {
                int row = warp_m * 64 + mi * 16 + (lane & 15);
                int kb  = kk * 32 + (lane >> 4) * 16;
                unsigned raw = row * 128 + kb;
                ldsm4(afr[mi], abase + (raw ^ ((row & 7) << 4)));
            }
            unsigned bfr[2][4];
#pragma unroll
            for (int g = 0; g < 2; g++) {
                int kr = kk * 16 + (lane & 15);
                int nb = (warp_n * 32 + g * 16 + (lane >> 4) * 8) * 2;
                unsigned raw = kr * 256 + nb;
                ldsm4t(bfr[g], bbase + (raw ^ ((kr & 7) << 4)));
            }
#pragma unroll
            for (int mi = 0; mi < 4; mi++)
#pragma unroll
                for (int nj = 0; nj < 4; nj++)
                    mma16816(acc[mi][nj], afr[mi][0], afr[mi][1], afr[mi][2],
                             afr[mi][3], bfr[nj >> 1][(nj & 1) * 2],
                             bfr[nj >> 1][(nj & 1) * 2 + 1]);
        }
    };

    issue(0, 0);
    const int NK = KDIM / KS;  // 16
    for (int ks = 0; ks < NK; ks++) {
        if (ks + 1 < NK) {
            issue(ks + 1, (ks + 1) & 1);
            asm volatile("cp.async.wait_group 1;\n" ::: "memory");
        } else {
            asm volatile("cp.async.wait_group 0;\n" ::: "memory");
        }
        __syncthreads();
        compute(ks & 1);
        __syncthreads();
    }

    // --- epilogue: bias + PReLU + stride-2 phase scatter (same as R2) ---
    const float alpha = prelu_a[0];
#pragma unroll
    for (int mi = 0; mi < 4; mi++) {
        const int rbase = warp_m * 64 + mi * 16 + (lane >> 2);
#pragma unroll
        for (int hm = 0; hm < 2; hm++) {
            const int co = rbase + hm * 8;
            const float bv = bias[co];
            float* obase = out + ((size_t)b * COUT + co) * OHW * OHW;
#pragma unroll
            for (int nj = 0; nj < 4; nj++) {
#pragma unroll
                for (int u = 0; u < 2; u++) {
                    int n  = n0 + warp_n * 32 + nj * 8 + (lane & 3) * 2 + u;
                    int y  = n >> 6;
                    int xx = n & 63;
                    int oy = 2 * y + py;
                    int ox = 2 * xx + px;
                    float v = acc[mi][nj][hm * 2 + u] + bv;
                    v = (v >= 0.f) ? v : alpha * v;
                    obase[oy * OHW + ox] = v;
                }
            }
        }
    }
}

// ---------------------------------------------------------------------------
// Launch
// ---------------------------------------------------------------------------
extern "C" void kernel_launch(void* const* d_in, const int* in_sizes, int n_in,
                              void* d_out, int out_size) {
    const float* x       = (const float*)d_in[0];
    const float* feature = (const float*)d_in[1];
    const float* weight  = (const float*)d_in[2];
    const float* t0      = (const float*)d_in[3];
    const float* t1      = (const float*)d_in[4];
    const float* t2      = (const float*)d_in[5];
    const float* t3      = (const float*)d_in[6];
    const float* m0      = (const float*)d_in[7];
    const float* m1      = (const float*)d_in[8];
    const float* m2      = (const float*)d_in[9];
    const float* m3      = (const float*)d_in[10];
    const float* bias    = (const float*)d_in[11];
    const float* prelu_a = (const float*)d_in[12];
    float* out = (float*)d_out;

    {
        int total = B_ * CIN * 66 * 8;
        prep_x_kernel<<<(total + 255) / 256, 256>>>(x);
    }
    {
        int total = CIN * COUT * 16;
        synth_kernel<<<(total + 255) / 256, 256>>>(feature, weight, t0, t1, t2, t3,
                                                   m0, m1, m2, m3);
    }
    {
        cudaFuncSetAttribute(deconv_mma_kernel,
                             cudaFuncAttributeMaxDynamicSharedMemorySize,
                             2 * STAGE_BYTES);
        dim3 grid(32, 4, B_);
        deconv_mma_kernel<<<grid, 256, 2 * STAGE_BYTES>>>(bias, prelu_a, out);
    }
}

// round 5
// speedup vs baseline: 6.7783x; 1.0971x over previous
#include <cuda_runtime.h>
#include <cuda_fp16.h>
#include <cstdint>

// Problem constants
#define B_    16
#define CIN   256
#define COUT  128
#define HW    64
#define OHW   128
#define KDIM  1024        // k' = q*256 + ci   (q = ty*2+tx tap index)
#define KS    64          // k' per pipeline stage
#define NK    16          // KDIM / KS
#define XP    66          // padded spatial extent
#define NSTG  3
#define STG_BYTES 32768   // A 16KB + B 16KB per stage

// Scratch
//  g_wsyn[b][p][co][k']   half, 16 MB
//  g_xc[b][row][col][ci]  half NHWC, zero border, 35.7 MB
__device__ __align__(16) __half g_wsyn[(size_t)B_ * 4 * COUT * KDIM];
__device__ __align__(16) __half g_xc[(size_t)B_ * XP * XP * CIN];

#define SWZ(o) ((o) ^ (((o) >> 3) & 0x70))

static __device__ __forceinline__ void mma16816(float c[4], unsigned a0, unsigned a1,
                                                unsigned a2, unsigned a3,
                                                unsigned b0, unsigned b1) {
    asm volatile(
        "mma.sync.aligned.m16n8k16.row.col.f32.f16.f16.f32 "
        "{%0,%1,%2,%3}, {%4,%5,%6,%7}, {%8,%9}, {%0,%1,%2,%3};\n"
        : "+f"(c[0]), "+f"(c[1]), "+f"(c[2]), "+f"(c[3])
        : "r"(a0), "r"(a1), "r"(a2), "r"(a3), "r"(b0), "r"(b1));
}
static __device__ __forceinline__ void ldsm4(unsigned r[4], unsigned addr) {
    asm volatile("ldmatrix.sync.aligned.m8n8.x4.shared.b16 {%0,%1,%2,%3}, [%4];"
                 : "=r"(r[0]), "=r"(r[1]), "=r"(r[2]), "=r"(r[3]) : "r"(addr));
}
static __device__ __forceinline__ void cpasync16(unsigned dst, const void* src) {
    asm volatile("cp.async.cg.shared.global [%0], [%1], 16;" :: "r"(dst), "l"(src));
}

// ---------------------------------------------------------------------------
// Fused front-end: prep (blocks 0..1055) + weight synth (blocks 1056..1311).
// prep: x (NCHW f32) -> g_xc (padded NHWC half). One CTA per (row, b).
// synth: -> half [b][p][co][k'], k' = q*256+ci, 16B stores.
// ---------------------------------------------------------------------------
#define PREP_BLOCKS (XP * B_)   // 1056

__global__ void __launch_bounds__(256) front_kernel(
    const float* __restrict__ x,
    const float* __restrict__ feature, const float* __restrict__ weight,
    const float* __restrict__ t0, const float* __restrict__ t1,
    const float* __restrict__ t2, const float* __restrict__ t3,
    const float* __restrict__ m0, const float* __restrict__ m1,
    const float* __restrict__ m2, const float* __restrict__ m3) {
    __shared__ __align__(16) __half sh[64 * 264];   // 33 KB (prep only)
    const int t = threadIdx.x;

    if (blockIdx.x < PREP_BLOCKS) {
        // ---------------- prep ----------------
        const int row = blockIdx.x % XP;
        const int b   = blockIdx.x / XP;
        __half* dst = g_xc + ((size_t)b * XP + row) * XP * CIN;

        if (row == 0 || row == XP - 1) {
            for (int i = t; i < XP * CIN / 8; i += 256)
                ((uint4*)dst)[i] = make_uint4(0, 0, 0, 0);
            return;
        }
        const int y = row - 1;
        const float* xr = x + (((size_t)b * CIN + t) * HW + y) * HW;
#pragma unroll
        for (int x4 = 0; x4 < 16; x4++) {
            float4 v = ((const float4*)xr)[x4];
            int xx = x4 * 4;
            sh[(xx + 0) * 264 + t] = __float2half(v.x);
            sh[(xx + 1) * 264 + t] = __float2half(v.y);
            sh[(xx + 2) * 264 + t] = __float2half(v.z);
            sh[(xx + 3) * 264 + t] = __float2half(v.w);
        }
        __syncthreads();
        {
            int col = 1 + (t >> 2);
            int ch  = (t & 3) * 64;
            uint4* d4 = (uint4*)(dst + (size_t)col * CIN + ch);
            const uint4* s4 = (const uint4*)(sh + (col - 1) * 264 + ch);
#pragma unroll
            for (int i = 0; i < 8; i++) d4[i] = s4[i];
        }
        if (t < 64) {
            int c = (t < 32) ? 0 : (XP - 1);
            ((uint4*)(dst + (size_t)c * CIN))[t & 31] = make_uint4(0, 0, 0, 0);
        }
    } else {
        // ---------------- synth ----------------
        __shared__ float sf[B_ * 4];
        if (t < B_ * 4) sf[t] = feature[t];
        __syncthreads();

        int idx = (blockIdx.x - PREP_BLOCKS) * 256 + t;   // over 32*128*16
        int kx  = idx & 3;
        int ky  = (idx >> 2) & 3;
        int co  = (idx >> 4) & (COUT - 1);
        int ci0 = (idx >> 11) * 8;

        float w[8], a0[8], a1[8], a2[8], a3[8];
#pragma unroll
        for (int i = 0; i < 8; i++) {
            int ci  = ci0 + i;
            int off = (ci * COUT + co) * 16 + ky * 4 + kx;
            int mi  = ci * COUT + co;
            w[i]  = weight[off];
            a0[i] = t0[off] * m0[mi];
            a1[i] = t1[off] * m1[mi];
            a2[i] = t2[off] * m2[mi];
            a3[i] = t3[off] * m3[mi];
        }
        int py = 1 - (ky & 1);
        int px = 1 - (kx & 1);
        int dy = (py + 1 - ky) / 2;
        int dx = (px + 1 - kx) / 2;
        int ty = dy + 1 - py;
        int tx = dx + 1 - px;
        int p  = py * 2 + px;
        int q  = ty * 2 + tx;

        size_t base     = ((size_t)p * COUT + co) * KDIM + q * 256 + ci0;
        size_t stride_b = (size_t)4 * COUT * KDIM;
#pragma unroll
        for (int b = 0; b < B_; b++) {
            const float* f = sf + b * 4;
            __align__(16) __half h[8];
#pragma unroll
            for (int i = 0; i < 8; i++)
                h[i] = __float2half(w[i] + a0[i] * f[0] + a1[i] * f[1] +
                                    a2[i] * f[2] + a3[i] * f[3]);
            *(uint4*)(g_wsyn + b * stride_b + base) = *(uint4*)h;
        }
    }
}

// ---------------------------------------------------------------------------
// GEMM: mma.sync m16n8k16, 3-stage cp.async pipeline, one sync per stage.
// CTA per (b, p, 128-spatial tile): M=128(co) x N=128(n) x K=1024.
// A[co][64k'] and B[n][64k'] both 128B swizzled rows; plain ldmatrix for both.
// 8 warps 2(m) x 4(n), warp tile 64x32.
// ---------------------------------------------------------------------------
__global__ void __launch_bounds__(256, 2)
deconv_mma_kernel(const float* __restrict__ bias,
                  const float* __restrict__ prelu_a,
                  float* __restrict__ out) {
    extern __shared__ __align__(1024) char smem[];
    const unsigned sb = (unsigned)__cvta_generic_to_shared(smem);
    const int tid  = threadIdx.x;
    const int lane = tid & 31;
    const int warp = tid >> 5;
    const int warp_m = warp >> 2;
    const int warp_n = warp & 3;
    const int b  = blockIdx.z;
    const int p  = blockIdx.y;
    const int py = p >> 1, px = p & 1;
    const int n0 = blockIdx.x * 128;
    const int y0 = n0 >> 6;

    const __half* wb = g_wsyn + (size_t)(b * 4 + p) * COUT * KDIM;
    const __half* xb = g_xc + (size_t)b * XP * XP * CIN;

    float acc[4][4][4];
#pragma unroll
    for (int i = 0; i < 4; i++)
#pragma unroll
        for (int j = 0; j < 4; j++)
#pragma unroll
            for (int r = 0; r < 4; r++) acc[i][j][r] = 0.f;

    auto fill = [&](int ks, int buf) {
        const unsigned ab = sb + buf * STG_BYTES;
        const unsigned bb = ab + 16384;
        const int k0 = ks * KS;
        // A: 128 co rows x 128B (contiguous k' segments)
#pragma unroll
        for (int i = 0; i < 4; i++) {
            int seg = tid + i * 256;
            int co = seg >> 3, s8 = seg & 7;
            cpasync16(ab + SWZ(co * 128 + s8 * 16),
                      wb + (size_t)co * KDIM + k0 + s8 * 8);
        }
        // B: 128 n rows x 128B (contiguous NHWC ci segments)
        const int q  = ks >> 2;
        const int ty = q >> 1, tx = q & 1;
        const int ci0 = (ks & 3) * 64;
#pragma unroll
        for (int i = 0; i < 4; i++) {
            int seg = tid + i * 256;
            int n = seg >> 3, s8 = seg & 7;
            int yy  = y0 + (n >> 6) + ty + py;
            int xx2 = (n & 63) + tx + px;
            cpasync16(bb + SWZ(n * 128 + s8 * 16),
                      xb + ((size_t)yy * XP + xx2) * CIN + ci0 + s8 * 8);
        }
        asm volatile("cp.async.commit_group;" ::: "memory");
    };

    auto compute = [&](int buf) {
        const unsigned ab = sb + buf * STG_BYTES;
        const unsigned bb = ab + 16384;
#pragma unroll
        for (int kk = 0; kk < 4; kk++) {
            const int kb = kk * 32 + (lane >> 4) * 16;
            unsigned afr[4][4];
#pragma unroll
            for (int mi = 0; mi < 4; mi++) {
                int row = warp_m * 64 + mi * 16 + (lane & 15);
                ldsm4(afr[mi], ab + SWZ(row * 128 + kb));
            }
            unsigned bfr[2][4];
#pragma unroll
            for (int g = 0; g < 2; g++) {
                int rown = warp_n * 32 + g * 16 + (lane & 15);
                ldsm4(bfr[g], bb + SWZ(rown * 128 + kb));
            }
#pragma unroll
            for (int mi = 0; mi < 4; mi++)
#pragma unroll
                for (int nj = 0; nj < 4; nj++)
                    mma16816(acc[mi][nj], afr[mi][0], afr[mi][1], afr[mi][2],
                             afr[mi][3], bfr[nj >> 1][nj & 1],
                             bfr[nj >> 1][(nj & 1) + 2]);
        }
    };

    fill(0, 0);
    fill(1, 1);
    for (int ks = 0; ks < NK; ks++) {
        if (ks == NK - 1)
            asm volatile("cp.async.wait_group 0;" ::: "memory");
        else
            asm volatile("cp.async.wait_group 1;" ::: "memory");
        __syncthreads();
        if (ks + 2 < NK) fill(ks + 2, (ks + 2) % NSTG);
        compute(ks % NSTG);
    }

    // --- epilogue: bias + PReLU + stride-2 phase scatter ---
    const float alpha = prelu_a[0];
#pragma unroll
    for (int mi = 0; mi < 4; mi++) {
        const int rbase = warp_m * 64 + mi * 16 + (lane >> 2);
#pragma unroll
        for (int hm = 0; hm < 2; hm++) {
            const int co = rbase + hm * 8;
            const float bv = bias[co];
            float* obase = out + ((size_t)b * COUT + co) * OHW * OHW;
#pragma unroll
            for (int nj = 0; nj < 4; nj++) {
#pragma unroll
                for (int u = 0; u < 2; u++) {
                    int n  = n0 + warp_n * 32 + nj * 8 + (lane & 3) * 2 + u;
                    int y  = n >> 6;
                    int xx = n & 63;
                    int oy = 2 * y + py;
                    int ox = 2 * xx + px;
                    float v = acc[mi][nj][hm * 2 + u] + bv;
                    v = (v >= 0.f) ? v : alpha * v;
                    obase[oy * OHW + ox] = v;
                }
            }
        }
    }
}

// ---------------------------------------------------------------------------
// Launch
// ---------------------------------------------------------------------------
extern "C" void kernel_launch(void* const* d_in, const int* in_sizes, int n_in,
                              void* d_out, int out_size) {
    const float* x       = (const float*)d_in[0];
    const float* feature = (const float*)d_in[1];
    const float* weight  = (const float*)d_in[2];
    const float* t0      = (const float*)d_in[3];
    const float* t1      = (const float*)d_in[4];
    const float* t2      = (const float*)d_in[5];
    const float* t3      = (const float*)d_in[6];
    const float* m0      = (const float*)d_in[7];
    const float* m1      = (const float*)d_in[8];
    const float* m2      = (const float*)d_in[9];
    const float* m3      = (const float*)d_in[10];
    const float* bias    = (const float*)d_in[11];
    const float* prelu_a = (const float*)d_in[12];
    float* out = (float*)d_out;

    {
        int blocks = PREP_BLOCKS + (CIN / 8) * COUT * 16 / 256;  // 1056 + 256
        front_kernel<<<blocks, 256>>>(x, feature, weight, t0, t1, t2, t3,
                                      m0, m1, m2, m3);
    }
    {
        cudaFuncSetAttribute(deconv_mma_kernel,
                             cudaFuncAttributeMaxDynamicSharedMemorySize,
                             NSTG * STG_BYTES);
        dim3 grid(HW * HW / 128, 4, B_);     // 32 x 4 x 16
        deconv_mma_kernel<<<grid, 256, NSTG * STG_BYTES>>>(bias, prelu_a, out);
    }
}